// round 16
// baseline (speedup 1.0000x reference)
#include <cuda_runtime.h>

// RotaryEmbedding: x (4,16,8192,64) fp32. Rotate first 4 pairs (elems 0..7)
// of each 64-float row; copy the remaining 56 floats unchanged.
//
// Evidence (R0-R15): hot floor ~35.3-35.7us across 4 independent request
// mechanisms (float4, TMA bulk, v8.b32, occupancy sweep); e2e = hot + ~8.5us
// constant writeback gap; hints/residency dead; bytes irreducible; noise 1.4.
//
// R16: persistent CTAs. grid=592 (148 SMs x 4 CTAs), each CTA grid-strides
// over ~7 tiles of 2048 float4s. Removes ~8 waves of CTA launch/drain churn
// ((n_waves-1)*T_wave_trans) and hoists tanh+sincos OUT of the tile loop
// (col4 = tid&15 is tile-invariant since 2048 % 16 == 0): coefficients
// computed once per thread for the whole kernel.

#define CHUNKS 8
#define TPB 256
#define PER_TILE (TPB * CHUNKS)     // 2048 float4s
#define GRID 592                    // 148 SMs x 4 resident CTAs

__global__ __launch_bounds__(TPB) void rope_persist(
    const float4* __restrict__ x,
    const float*  __restrict__ dparam,
    const float*  __restrict__ thetas,
    float4*       __restrict__ out,
    int n_tiles)
{
    const int tid = threadIdx.x;
    const int col4 = tid & 15;      // tile-invariant: PER_TILE % 16 == 0

    // Coefficients once per thread (rotating lanes only: 4 of 32 per warp)
    float c0 = 1.f, s0 = 0.f, c1 = 1.f, s1 = 0.f;
    if (col4 < 2) {
        float d = tanhf(0.5f * dparam[0]);     // sigmoid(d)*2 - 1
        int p = col4 * 2;
        sincosf(d * thetas[p],     &s0, &c0);
        sincosf(d * thetas[p + 1], &s1, &c1);
    }

    for (int tile = blockIdx.x; tile < n_tiles; tile += GRID) {
        int base = tile * PER_TILE + tid;

        float4 v[CHUNKS];
        #pragma unroll
        for (int k = 0; k < CHUNKS; k++)
            v[k] = x[base + k * TPB];

        if (col4 < 2) {
            #pragma unroll
            for (int k = 0; k < CHUNKS; k++) {
                float xi0 = v[k].x, xj0 = v[k].y;
                float xi1 = v[k].z, xj1 = v[k].w;
                v[k].x =  xi0 * c0 + xj0 * s0;
                v[k].y = -xi0 * s0 + xj0 * c0;
                v[k].z =  xi1 * c1 + xj1 * s1;
                v[k].w = -xi1 * s1 + xj1 * c1;
            }
        }

        #pragma unroll
        for (int k = 0; k < CHUNKS; k++)
            out[base + k * TPB] = v[k];
    }
}

// Guarded fallback (not taken for the bench shape).
__global__ __launch_bounds__(TPB) void rope_guarded(
    const float4* __restrict__ x,
    const float*  __restrict__ dparam,
    const float*  __restrict__ thetas,
    float4*       __restrict__ out,
    int n4)
{
    int i = blockIdx.x * TPB + threadIdx.x;
    if (i >= n4) return;
    float4 v = x[i];
    int col4 = i & 15;
    if (col4 < 2) {
        float d = tanhf(0.5f * dparam[0]);
        int p = col4 * 2;
        float s0, c0, s1, c1;
        sincosf(d * thetas[p],     &s0, &c0);
        sincosf(d * thetas[p + 1], &s1, &c1);
        float xi0 = v.x, xj0 = v.y, xi1 = v.z, xj1 = v.w;
        v.x =  xi0 * c0 + xj0 * s0;
        v.y = -xi0 * s0 + xj0 * c0;
        v.z =  xi1 * c1 + xj1 * s1;
        v.w = -xi1 * s1 + xj1 * c1;
    }
    out[i] = v;
}

extern "C" void kernel_launch(void* const* d_in, const int* in_sizes, int n_in,
                              void* d_out, int out_size)
{
    const float4* x      = (const float4*)d_in[0];
    const float*  dparam = (const float*)d_in[1];
    const float*  thetas = (const float*)d_in[2];
    float4*       out    = (float4*)d_out;

    int n4 = in_sizes[0] / 4;                   // 8,388,608 float4 chunks
    if (n4 % PER_TILE == 0) {
        int n_tiles = n4 / PER_TILE;            // 4096
        rope_persist<<<GRID, TPB>>>(x, dparam, thetas, out, n_tiles);
    } else {
        rope_guarded<<<(n4 + TPB - 1) / TPB, TPB>>>(x, dparam, thetas, out, n4);
    }
}

// round 17
// speedup vs baseline: 1.0908x; 1.0908x over previous
#include <cuda_runtime.h>

// RotaryEmbedding: x (4,16,8192,64) fp32. Rotate first 4 pairs (elems 0..7)
// of each 64-float row; copy the remaining 56 floats unchanged.
//
// FINAL — converged optimum (R3 config, best measured e2e 43.5us, twice).
//
// Session map (R0-R16), all axes exhausted:
//   - Request mechanism: float4 LDG == TMA bulk == v8.b32 (hot 35.3-35.7us)
//     -> memory system limits, not request supply.
//   - Bytes irreducible: 134MB read + 134MB write; e2e = 268MB / ~6.15TB/s
//     sustained mixed-R/W BW + const ~8.5us writeback drain over ncu-hot.
//   - L2 residency blocked: evict_last requires persisting carveout (=0;
//     knob harness-forbidden). All cache hints (.cs matrix, createpolicy)
//     regress or null — default policy optimal.
//   - Reg caps spill (never cap); CHUNKSxTPB sweep RF-invariant (occ*MLP
//     product fixed); persistent CTAs serialize load/store batches (WAR on
//     register tiles) — independent short-lived CTAs win for streaming.
//   - run-to-run noise +-1.4us.

#define CHUNKS 8
#define TPB 256

__device__ __forceinline__ void rope_math(float4 v[CHUNKS], int col4,
                                          const float* __restrict__ dparam,
                                          const float* __restrict__ thetas)
{
    if (col4 < 2) {
        // direction = sigmoid(d)*2 - 1 = tanh(d/2)
        float d = tanhf(0.5f * dparam[0]);
        int p = col4 * 2;
        float s0, c0, s1, c1;
        sincosf(d * thetas[p],     &s0, &c0);
        sincosf(d * thetas[p + 1], &s1, &c1);
        #pragma unroll
        for (int k = 0; k < CHUNKS; k++) {
            float xi0 = v[k].x, xj0 = v[k].y;
            float xi1 = v[k].z, xj1 = v[k].w;
            v[k].x =  xi0 * c0 + xj0 * s0;
            v[k].y = -xi0 * s0 + xj0 * c0;
            v[k].z =  xi1 * c1 + xj1 * s1;
            v[k].w = -xi1 * s1 + xj1 * c1;
        }
    }
}

// Fast path: grid covers n4 exactly, no guards.
__global__ __launch_bounds__(TPB) void rope8_exact(
    const float4* __restrict__ x,
    const float*  __restrict__ dparam,
    const float*  __restrict__ thetas,
    float4*       __restrict__ out)
{
    int base = blockIdx.x * (TPB * CHUNKS) + threadIdx.x;

    float4 v[CHUNKS];
    #pragma unroll
    for (int k = 0; k < CHUNKS; k++)
        v[k] = x[base + k * TPB];

    rope_math(v, base & 15, dparam, thetas);   // TPB=256: col4 invariant

    #pragma unroll
    for (int k = 0; k < CHUNKS; k++)
        out[base + k * TPB] = v[k];
}

// Guarded fallback (not taken for the bench shape).
__global__ __launch_bounds__(TPB) void rope8_guarded(
    const float4* __restrict__ x,
    const float*  __restrict__ dparam,
    const float*  __restrict__ thetas,
    float4*       __restrict__ out,
    int n4)
{
    int base = blockIdx.x * (TPB * CHUNKS) + threadIdx.x;

    float4 v[CHUNKS];
    #pragma unroll
    for (int k = 0; k < CHUNKS; k++) {
        int i = base + k * TPB;
        if (i < n4) v[k] = x[i];
    }

    rope_math(v, base & 15, dparam, thetas);

    #pragma unroll
    for (int k = 0; k < CHUNKS; k++) {
        int i = base + k * TPB;
        if (i < n4) out[i] = v[k];
    }
}

extern "C" void kernel_launch(void* const* d_in, const int* in_sizes, int n_in,
                              void* d_out, int out_size)
{
    const float4* x      = (const float4*)d_in[0];
    const float*  dparam = (const float*)d_in[1];
    const float*  thetas = (const float*)d_in[2];
    float4*       out    = (float4*)d_out;

    int n4 = in_sizes[0] / 4;                   // 8,388,608 float4 chunks
    const int per_block = TPB * CHUNKS;         // 2048
    if (n4 % per_block == 0) {
        rope8_exact<<<n4 / per_block, TPB>>>(x, dparam, thetas, out);
    } else {
        int blocks = (n4 + per_block - 1) / per_block;
        rope8_guarded<<<blocks, TPB>>>(x, dparam, thetas, out, n4);
    }
}